// round 15
// baseline (speedup 1.0000x reference)
#include <cuda_runtime.h>
#include <cuda_bf16.h>
#include <stdint.h>
#include <math.h>

#define BB 2
#define NN 2048
#define CC 1024
#define HH 16
#define HD 64
#define M_ROWS (BB*NN)   // 4096

// ---------------- device scratch (allocation-free) ----------------
__device__ __nv_bfloat16 g_x_hi[M_ROWS * CC];
__device__ __nv_bfloat16 g_w1_hi[3 * CC * CC];
__device__ __nv_bfloat16 g_w2_hi[CC * CC];
// head-major [b*H+h][sorted n][64] bf16
__device__ __nv_bfloat16 g_qn[BB * HH * NN * HD];
__device__ __nv_bfloat16 g_kn[BB * HH * NN * HD];
__device__ __nv_bfloat16 g_vh[BB * HH * NN * HD];
__device__ float g_xpart[64 * BB * CC];               // xsum partials
__device__ float g_xsum[BB * CC];
__device__ float g_vsum[BB * CC];                     // exact colsum of V
__device__ float g_vsumw[BB * CC];                    // vsum . W2^T
// score sort
__device__ float g_ssort[NN];                         // scores sorted desc
__device__ int   g_perm[NN];                          // sorted pos -> orig token
__device__ int   g_inv[NN];                           // orig token -> sorted pos
// attention deviation output (bf16) + per-row 1/l
__device__ __nv_bfloat16 g_dev[M_ROWS * CC];
__device__ float g_invl[M_ROWS];

// ---------------------------------------------------------------------------
// Merged converts: blocks [0,16384) convert w1|w2; blocks [16384,16896)
// convert x -> bf16 and emit column-sum partials (same mapping as before).
// ---------------------------------------------------------------------------
__global__ __launch_bounds__(256) void cvt_kernel(
    const float* __restrict__ w1, const float* __restrict__ w2,
    const float* __restrict__ x)
{
    int bid = blockIdx.x;
    int tid = threadIdx.x;
    if (bid < 16384) {
        int i = bid * 256 + tid;
        const int n1 = 3 * CC * CC;
        if (i < n1) g_w1_hi[i] = __float2bfloat16(w1[i]);
        else        g_w2_hi[i - n1] = __float2bfloat16(w2[i - n1]);
    } else {
        int b2 = bid - 16384;             // 0..511
        int chunk = b2 >> 3;              // 0..63
        int c = (b2 & 7) * 256 + tid;     // 0..2047
        int b = c >> 10;
        size_t base = (size_t)b * NN * CC + (size_t)chunk * 32 * CC + (c & 1023);
        float s = 0.0f;
        #pragma unroll 8
        for (int n = 0; n < 32; ++n) {
            float v = x[base + (size_t)n * CC];
            g_x_hi[base + (size_t)n * CC] = __float2bfloat16(v);
            s += v;
        }
        g_xpart[chunk * (BB * CC) + c] = s;
    }
}

__global__ __launch_bounds__(256) void xsum_final_kernel()
{
    int c = blockIdx.x * 256 + threadIdx.x;
    float s = 0.0f;
    #pragma unroll
    for (int t = 0; t < 64; ++t) s += g_xpart[t * (BB * CC) + c];
    g_xsum[c] = s;
}

__global__ __launch_bounds__(256) void vsumx_kernel(const float* __restrict__ w)
{
    int gw = (blockIdx.x * 256 + threadIdx.x) >> 5;
    int lane = threadIdx.x & 31;
    int b = gw >> 10, dfull = gw & 1023;
    const float* wr = w + (size_t)(2048 + dfull) * CC;
    const float* xs = g_xsum + b * CC;
    float s = 0.0f;
    #pragma unroll 8
    for (int i = lane; i < CC; i += 32) s += xs[i] * wr[i];
    #pragma unroll
    for (int o = 16; o; o >>= 1) s += __shfl_xor_sync(0xffffffffu, s, o);
    if (lane == 0) g_vsum[b * CC + dfull] = s;
}

__global__ __launch_bounds__(256) void vsumw_kernel(const float* __restrict__ w2)
{
    int gw = (blockIdx.x * 256 + threadIdx.x) >> 5;
    int lane = threadIdx.x & 31;
    int b = gw >> 10, cout = gw & 1023;
    const float* wr = w2 + (size_t)cout * CC;
    const float* vs = g_vsum + b * CC;
    float s = 0.0f;
    #pragma unroll 8
    for (int i = lane; i < CC; i += 32) s += vs[i] * wr[i];
    #pragma unroll
    for (int o = 16; o; o >>= 1) s += __shfl_xor_sync(0xffffffffu, s, o);
    if (lane == 0) g_vsumw[b * CC + cout] = s;
}

// ---------------------------------------------------------------------------
// Bitonic sort of 2048 scores (descending) -> g_ssort / g_perm / g_inv.
// ---------------------------------------------------------------------------
__global__ __launch_bounds__(1024) void sort_kernel(const float* __restrict__ cls)
{
    __shared__ float ss[NN];
    __shared__ int   si[NN];
    int tid = threadIdx.x;
    for (int i = tid; i < NN; i += 1024) { ss[i] = cls[i]; si[i] = i; }
    __syncthreads();
    for (int k = 2; k <= NN; k <<= 1) {
        for (int j = k >> 1; j > 0; j >>= 1) {
            for (int i = tid; i < NN; i += 1024) {
                int ixj = i ^ j;
                if (ixj > i) {
                    bool up = ((i & k) == 0);
                    float a = ss[i], c = ss[ixj];
                    bool sw = up ? (a < c) : (a > c);
                    if (sw) {
                        ss[i] = c; ss[ixj] = a;
                        int t = si[i]; si[i] = si[ixj]; si[ixj] = t;
                    }
                }
            }
            __syncthreads();
        }
    }
    for (int i = tid; i < NN; i += 1024) {
        g_ssort[i] = ss[i];
        g_perm[i] = si[i];
        g_inv[si[i]] = i;
    }
}

// ---------------- mma helpers ----------------
__device__ __forceinline__ unsigned smem_u32(const void* p) {
    return (unsigned)__cvta_generic_to_shared(p);
}
__device__ __forceinline__ void cp16(void* smem, const void* gmem) {
    unsigned sa = smem_u32(smem);
    asm volatile("cp.async.cg.shared.global [%0], [%1], 16;\n" :: "r"(sa), "l"(gmem));
}
__device__ __forceinline__ void ldsm4(unsigned r[4], const void* p) {
    unsigned a = smem_u32(p);
    asm volatile("ldmatrix.sync.aligned.m8n8.x4.shared.b16 {%0,%1,%2,%3}, [%4];"
                 : "=r"(r[0]), "=r"(r[1]), "=r"(r[2]), "=r"(r[3]) : "r"(a));
}
__device__ __forceinline__ void ldsm4t(unsigned r[4], const void* p) {
    unsigned a = smem_u32(p);
    asm volatile("ldmatrix.sync.aligned.m8n8.x4.trans.shared.b16 {%0,%1,%2,%3}, [%4];"
                 : "=r"(r[0]), "=r"(r[1]), "=r"(r[2]), "=r"(r[3]) : "r"(a));
}
__device__ __forceinline__ void mma16816(float c[4], const unsigned a[4],
                                         unsigned b0, unsigned b1) {
    asm volatile(
        "mma.sync.aligned.m16n8k16.row.col.f32.bf16.bf16.f32 "
        "{%0,%1,%2,%3}, {%4,%5,%6,%7}, {%8,%9}, {%0,%1,%2,%3};"
        : "+f"(c[0]), "+f"(c[1]), "+f"(c[2]), "+f"(c[3])
        : "r"(a[0]), "r"(a[1]), "r"(a[2]), "r"(a[3]), "r"(b0), "r"(b1));
}
// delta = exp(t)-1 for |t|<=0.125 via cubic (residual <= t^4/24 ~ 1e-5)
__device__ __forceinline__ float expm1c(float t) {
    return t * fmaf(t, fmaf(t, 0.16666667f, 0.5f), 1.0f);
}

#define GLDA 40
#define TILE_B (128 * GLDA * 2)   // 10240 B per 128x32 bf16 tile

// ---------------------------------------------------------------------------
// Single-pass bf16 GEMM (NT), 4-stage cp.async pipeline, 2 CTAs/SM.
// MODE=1: C = A B^T + invl[m]*vsumw[b][n] + bias[n]   (output projection)
// MODE=2: qkv fused epilogue (norm/split/sort-permute), no C write.
// ---------------------------------------------------------------------------
template<int MODE>
__global__ __launch_bounds__(256, 2) void gemm1p_kernel(
    const __nv_bfloat16* __restrict__ A, const __nv_bfloat16* __restrict__ Bm,
    float* __restrict__ C, int Nn,
    const float* __restrict__ invl, const float* __restrict__ vsumw,
    const float* __restrict__ bias)
{
    extern __shared__ char sm_raw[];
    const int STAGE = 2 * TILE_B;
    int tid = threadIdx.x;
    int lane = tid & 31;
    int wid = tid >> 5;
    int warp_m = wid >> 2;
    int warp_n = wid & 3;
    int m0 = blockIdx.y * 128;
    int n0 = blockIdx.x * 128;

    float acc[4][4][4];
    #pragma unroll
    for (int mi = 0; mi < 4; ++mi)
        #pragma unroll
        for (int j = 0; j < 4; ++j)
            #pragma unroll
            for (int e = 0; e < 4; ++e) acc[mi][j][e] = 0.0f;

    auto load_stage = [&](int kt, int s) {
        char* sb = sm_raw + s * STAGE;
        int k0 = kt * 32;
        #pragma unroll
        for (int t = 0; t < 4; ++t) {
            int c = tid + t * 256;
            int arr = c >> 9;
            int r = (c >> 2) & 127;
            int c16 = c & 3;
            const __nv_bfloat16* g =
                (arr ? Bm : A) + (size_t)((arr ? n0 : m0) + r) * CC + k0 + c16 * 8;
            cp16(sb + arr * TILE_B + r * (GLDA * 2) + c16 * 16, g);
        }
    };

    const int KT = CC / 32;
    load_stage(0, 0); asm volatile("cp.async.commit_group;");
    load_stage(1, 1); asm volatile("cp.async.commit_group;");
    load_stage(2, 2); asm volatile("cp.async.commit_group;");

    for (int kt = 0; kt < KT; ++kt) {
        if (kt + 2 < KT)      asm volatile("cp.async.wait_group 2;");
        else if (kt + 1 < KT) asm volatile("cp.async.wait_group 1;");
        else                  asm volatile("cp.async.wait_group 0;");
        __syncthreads();
        const char* As = sm_raw + (kt & 3) * STAGE;
        const char* Bs = As + TILE_B;

        #pragma unroll
        for (int ks = 0; ks < 32; ks += 16) {
            int coloff = ks + ((lane >> 4) << 3);
            unsigned ah[4][4];
            #pragma unroll
            for (int mi = 0; mi < 4; ++mi)
                ldsm4(ah[mi], As + (warp_m * 64 + mi * 16 + (lane & 15)) * (GLDA * 2)
                               + coloff * 2);
            unsigned bh[2][4];
            #pragma unroll
            for (int ni = 0; ni < 2; ++ni)
                ldsm4(bh[ni], Bs + (warp_n * 32 + ni * 16 + (lane & 15)) * (GLDA * 2)
                               + coloff * 2);
            #pragma unroll
            for (int mi = 0; mi < 4; ++mi)
                #pragma unroll
                for (int j = 0; j < 4; ++j) {
                    int ni = j >> 1, od = j & 1;
                    mma16816(acc[mi][j], ah[mi],
                             bh[ni][od ? 1 : 0], bh[ni][od ? 3 : 2]);
                }
        }
        if (kt + 3 < KT) {
            load_stage(kt + 3, (kt + 3) & 3);
            asm volatile("cp.async.commit_group;");
        }
    }

    if (MODE == 1) {
        int mb = m0 + warp_m * 64 + (lane >> 2);
        int nb = n0 + warp_n * 32 + 2 * (lane & 3);
        #pragma unroll
        for (int mi = 0; mi < 4; ++mi)
            #pragma unroll
            for (int j = 0; j < 4; ++j) {
                int col = nb + j * 8;
                int r0 = mb + mi * 16;
                int b = r0 >> 11;
                float b0 = bias[col], b1 = bias[col + 1];
                float vw0 = vsumw[b * CC + col], vw1 = vsumw[b * CC + col + 1];
                float il0 = invl[r0], il8 = invl[r0 + 8];
                float a0 = acc[mi][j][0] + il0 * vw0 + b0;
                float a1 = acc[mi][j][1] + il0 * vw1 + b1;
                float a2 = acc[mi][j][2] + il8 * vw0 + b0;
                float a3 = acc[mi][j][3] + il8 * vw1 + b1;
                *reinterpret_cast<float2*>(&C[(size_t)r0 * Nn + col]) =
                    make_float2(a0, a1);
                *reinterpret_cast<float2*>(&C[(size_t)(r0 + 8) * Nn + col]) =
                    make_float2(a2, a3);
            }
    } else {
        int part = n0 >> 10;                     // 0=q, 1=k, 2=v
        int h = ((n0 & 1023) >> 6) + (warp_n >> 1);
        float* red = (float*)sm_raw;
        __syncthreads();

        if (part < 2) {
            #pragma unroll
            for (int mi = 0; mi < 4; ++mi) {
                float s0 = 0.0f, s8 = 0.0f;
                #pragma unroll
                for (int j = 0; j < 4; ++j) {
                    s0 += acc[mi][j][0] * acc[mi][j][0] + acc[mi][j][1] * acc[mi][j][1];
                    s8 += acc[mi][j][2] * acc[mi][j][2] + acc[mi][j][3] * acc[mi][j][3];
                }
                s0 += __shfl_xor_sync(0xffffffffu, s0, 1);
                s0 += __shfl_xor_sync(0xffffffffu, s0, 2);
                s8 += __shfl_xor_sync(0xffffffffu, s8, 1);
                s8 += __shfl_xor_sync(0xffffffffu, s8, 2);
                if ((lane & 3) == 0) {
                    int lr = warp_m * 64 + mi * 16 + (lane >> 2);
                    red[warp_n * 128 + lr] = s0;
                    red[warp_n * 128 + lr + 8] = s8;
                }
            }
            __syncthreads();
        }

        float qsc = (part == 0) ? 0.125f : 1.0f;
        __nv_bfloat16* dst = (part == 0) ? g_qn : (part == 1 ? g_kn : g_vh);
        int pbase = (warp_n & 2) * 128;
        int dbase = (warp_n & 1) * 32 + 2 * (lane & 3);

        #pragma unroll
        for (int mi = 0; mi < 4; ++mi) {
            int lr0 = warp_m * 64 + mi * 16 + (lane >> 2);
            int r0 = m0 + lr0;
            float inv0 = 1.0f, inv8 = 1.0f;
            if (part < 2) {
                float s0 = red[pbase + lr0] + red[pbase + 128 + lr0];
                float s8 = red[pbase + lr0 + 8] + red[pbase + 128 + lr0 + 8];
                inv0 = qsc / (sqrtf(s0) + 1e-8f);
                inv8 = qsc / (sqrtf(s8) + 1e-8f);
            }
            int b = r0 >> 11;
            int pos0 = g_inv[r0 & 2047];
            int pos8 = g_inv[(r0 + 8) & 2047];
            size_t base0 = ((size_t)(b * HH + h) * NN + pos0) * 64;
            size_t base8 = ((size_t)(b * HH + h) * NN + pos8) * 64;
            #pragma unroll
            for (int j = 0; j < 4; ++j) {
                int d = dbase + j * 8;
                __nv_bfloat162 v0 =
                    __floats2bfloat162_rn(acc[mi][j][0] * inv0, acc[mi][j][1] * inv0);
                __nv_bfloat162 v8 =
                    __floats2bfloat162_rn(acc[mi][j][2] * inv8, acc[mi][j][3] * inv8);
                *reinterpret_cast<__nv_bfloat162*>(dst + base0 + d) = v0;
                *reinterpret_cast<__nv_bfloat162*>(dst + base8 + d) = v8;
            }
        }
    }
}

// ---------------------------------------------------------------------------
// Attention tile body. MASK=false: full-tile fast path (no SELs).
// delta via cubic expm1 (no MUFU); V fragments hoisted before softmax.
// ---------------------------------------------------------------------------
#define ATS 72
#define KTB (128 * ATS * 2)

template<bool MASK>
__device__ __forceinline__ void attn_tile(
    const char* Kb, const char* Vhb, const float* sk,
    const unsigned qa[4][4], float sq0, float sq8,
    float o[8][4], float& l0, float& l8, int lane, int c2)
{
    #pragma unroll
    for (int j = 0; j < 8; ++j) {
        float cc[2][4] = {{0, 0, 0, 0}, {0, 0, 0, 0}};
        int krow = 16 * j + (lane & 15);
        // K fragments + QK mma
        #pragma unroll
        for (int dc = 0; dc < 4; ++dc) {
            unsigned kb[4];
            ldsm4(kb, Kb + krow * (ATS * 2) + (16 * dc + ((lane >> 4) << 3)) * 2);
            mma16816(cc[0], qa[dc], kb[0], kb[2]);
            mma16816(cc[1], qa[dc], kb[1], kb[3]);
        }
        // V fragments: independent of softmax — issue early to hide LDS latency
        unsigned vb[4][4];
        #pragma unroll
        for (int n2 = 0; n2 < 4; ++n2)
            ldsm4t(vb[n2], Vhb + krow * (ATS * 2)
                           + (16 * n2 + ((lane >> 4) << 3)) * 2);
        // softmax delta (cubic expm1, FMA-pipe only)
        unsigned ad[4];
        #pragma unroll
        for (int t = 0; t < 2; ++t) {
            float2 skv = *reinterpret_cast<const float2*>(&sk[16 * j + 8 * t + c2]);
            float fx0 = skv.x, fy0 = skv.y, fx8 = skv.x, fy8 = skv.y;
            if (MASK) {
                fx0 = (skv.x > sq0) ? skv.x : 0.0f;
                fy0 = (skv.y > sq0) ? skv.y : 0.0f;
                fx8 = (skv.x > sq8) ? skv.x : 0.0f;
                fy8 = (skv.y > sq8) ? skv.y : 0.0f;
            }
            float d00 = expm1c(cc[t][0] * fx0);
            float d01 = expm1c(cc[t][1] * fy0);
            float d80 = expm1c(cc[t][2] * fx8);
            float d81 = expm1c(cc[t][3] * fy8);
            l0 += d00 + d01;
            l8 += d80 + d81;
            __nv_bfloat162 D0 = __floats2bfloat162_rn(d00, d01);
            __nv_bfloat162 D8 = __floats2bfloat162_rn(d80, d81);
            ad[2 * t]     = *reinterpret_cast<unsigned*>(&D0);
            ad[2 * t + 1] = *reinterpret_cast<unsigned*>(&D8);
        }
        // PV mma
        #pragma unroll
        for (int n2 = 0; n2 < 4; ++n2) {
            mma16816(o[2 * n2],     ad, vb[n2][0], vb[n2][1]);
            mma16816(o[2 * n2 + 1], ad, vb[n2][2], vb[n2][3]);
        }
    }
}

// ---------------------------------------------------------------------------
// Tensor-core attention, delta-trick + sorted prefix skipping, PAIRED q-tiles.
// ---------------------------------------------------------------------------
__global__ __launch_bounds__(256, 2) void attn_mma_kernel(const int* __restrict__ um_p)
{
    extern __shared__ char smem[];
    float* sks = (float*)(smem + 4 * KTB);
    __shared__ float sh_full[2][16];
    __shared__ int sh_ktstop[2];

    int tid = threadIdx.x;
    int lane = tid & 31;
    int warp = tid >> 5;
    int qpair = blockIdx.x;                // 0..7
    int bh = blockIdx.y;
    int b = bh >> 4, h = bh & 15;
    int um = um_p[0];
    int r = lane >> 2;
    int c2 = 2 * (lane & 3);

    if (tid < 2) {
        int qt = tid ? (15 - qpair) : qpair;
        float sqmin = g_ssort[qt * 128 + 127];
        int ks = 16;
        if (um) {
            for (int t = 1; t < 16; ++t)
                if (g_ssort[t * 128] <= sqmin - 0.1f) { ks = t; break; }
        }
        sh_ktstop[tid] = ks;
    }
    if (tid < 32) {
        int hf = tid >> 4, t = tid & 15;
        int qt = hf ? (15 - qpair) : qpair;
        float sqmax = g_ssort[qt * 128];
        float skmin = g_ssort[t * 128 + 127];
        sh_full[hf][t] = (um == 0 || skmin > sqmax - 0.1f) ? 1.0f : 0.0f;
    }

    const __nv_bfloat16* kg  = g_kn + (size_t)bh * NN * 64;
    const __nv_bfloat16* vhg = g_vh + (size_t)bh * NN * 64;

    auto stage_load = [&](int kt, int s) {
        #pragma unroll
        for (int t = 0; t < 8; ++t) {
            int cix = tid + t * 256;
            int arr = cix >> 10;
            int rr  = (cix >> 3) & 127;
            int seg = cix & 7;
            const __nv_bfloat16* gb = (arr == 0) ? kg : vhg;
            const __nv_bfloat16* g = gb + ((size_t)(kt * 128 + rr)) * 64 + seg * 8;
            cp16(smem + arr * 2 * KTB + s * KTB + rr * (ATS * 2) + seg * 16, g);
        }
        if (tid < 128) sks[s * 128 + tid] = g_ssort[kt * 128 + tid];
    };

    for (int hf = 0; hf < 2; ++hf) {
        int q0 = (hf ? (15 - qpair) : qpair) * 128;

        const __nv_bfloat16* qg = g_qn + ((size_t)bh * NN + q0 + warp * 16) * 64;
        unsigned qa[4][4];
        #pragma unroll
        for (int dc = 0; dc < 4; ++dc) {
            qa[dc][0] = *(const unsigned*)(qg + (size_t)r * 64 + 16 * dc + c2);
            qa[dc][1] = *(const unsigned*)(qg + (size_t)(r + 8) * 64 + 16 * dc + c2);
            qa[dc][2] = *(const unsigned*)(qg + (size_t)r * 64 + 16 * dc + 8 + c2);
            qa[dc][3] = *(const unsigned*)(qg + (size_t)(r + 8) * 64 + 16 * dc + 8 + c2);
        }
        float sq0 = g_ssort[q0 + warp * 16 + r] - 0.1f;
        float sq8 = g_ssort[q0 + warp * 16 + r + 8] - 0.1f;

        float o[8][4];
        #pragma unroll
        for (int i = 0; i < 8; ++i)
            #pragma unroll
            for (int e = 0; e < 4; ++e) o[i][e] = 0.0f;
        float l0 = 0.0f, l8 = 0.0f;

        __syncthreads();
        const int KTS = sh_ktstop[hf];

        stage_load(0, 0);
        asm volatile("cp.async.commit_group;");

        for (int kt = 0; kt < KTS; ++kt) {
            asm volatile("cp.async.wait_group 0;");
            __syncthreads();
            if (kt + 1 < KTS) {
                stage_load(kt + 1, (kt + 1) & 1);
                asm volatile("cp.async.commit_group;");
            }
            int s = kt & 1;
            const char* Kb  = smem + s * KTB;
            const char* Vhb = smem + 2 * KTB + s * KTB;
            const float* sk = sks + s * 128;
            if (sh_full[hf][kt] != 0.0f)
                attn_tile<false>(Kb, Vhb, sk, qa, sq0, sq8, o, l0, l8, lane, c2);
            else
                attn_tile<true>(Kb, Vhb, sk, qa, sq0, sq8, o, l0, l8, lane, c2);
        }

        l0 += __shfl_xor_sync(0xffffffffu, l0, 1);
        l0 += __shfl_xor_sync(0xffffffffu, l0, 2);
        l8 += __shfl_xor_sync(0xffffffffu, l8, 1);
        l8 += __shfl_xor_sync(0xffffffffu, l8, 2);
        // l = sum p = (count of all keys: processed 1+delta, masked/skipped 1)
        float inv0 = 1.0f / ((float)NN + l0);
        float inv8 = 1.0f / ((float)NN + l8);

        int qrow = q0 + warp * 16 + r;
        int orig0 = g_perm[qrow];
        int orig8 = g_perm[qrow + 8];
        size_t tok0 = (size_t)(b * NN + orig0);
        size_t tok8 = (size_t)(b * NN + orig8);
        if ((lane & 3) == 0) {
            g_invl[tok0] = inv0;
            g_invl[tok8] = inv8;
        }
        size_t row0 = tok0 * CC + h * 64;
        size_t row8 = tok8 * CC + h * 64;
        #pragma unroll
        for (int nt = 0; nt < 8; ++nt) {
            int d = 8 * nt + c2;
            *reinterpret_cast<__nv_bfloat162*>(&g_dev[row0 + d]) =
                __floats2bfloat162_rn(o[nt][0] * inv0, o[nt][1] * inv0);
            *reinterpret_cast<__nv_bfloat162*>(&g_dev[row8 + d]) =
                __floats2bfloat162_rn(o[nt][2] * inv8, o[nt][3] * inv8);
        }
    }
}

// ---------------------------------------------------------------------------
// Launch
// ---------------------------------------------------------------------------
static const int GEMM1P_SMEM = 4 * 2 * TILE_B;
static const int ATTN_SMEM_BYTES = 4 * KTB + 2 * 128 * (int)sizeof(float);

extern "C" void kernel_launch(void* const* d_in, const int* in_sizes, int n_in,
                              void* d_out, int out_size)
{
    const float* x     = (const float*)d_in[0];
    const float* cls   = (const float*)d_in[1];
    const float* qkvw  = (const float*)d_in[2];
    const float* projw = (const float*)d_in[3];
    const float* projb = (const float*)d_in[4];
    const int*   um    = (const int*)d_in[5];
    float* out = (float*)d_out;

    float *invl, *vsumw;
    __nv_bfloat16 *xh, *w1h, *w2h, *dev;
    cudaGetSymbolAddress((void**)&xh,    g_x_hi);
    cudaGetSymbolAddress((void**)&w1h,   g_w1_hi);
    cudaGetSymbolAddress((void**)&w2h,   g_w2_hi);
    cudaGetSymbolAddress((void**)&dev,   g_dev);
    cudaGetSymbolAddress((void**)&invl,  g_invl);
    cudaGetSymbolAddress((void**)&vsumw, g_vsumw);

    cudaFuncSetAttribute(gemm1p_kernel<1>,
                         cudaFuncAttributeMaxDynamicSharedMemorySize, GEMM1P_SMEM);
    cudaFuncSetAttribute(gemm1p_kernel<2>,
                         cudaFuncAttributeMaxDynamicSharedMemorySize, GEMM1P_SMEM);
    cudaFuncSetAttribute(attn_mma_kernel,
                         cudaFuncAttributeMaxDynamicSharedMemorySize, ATTN_SMEM_BYTES);

    dim3 blk(256);

    // score sort (g_inv needed by qkv gemm epilogue)
    sort_kernel<<<1, 1024>>>(cls);

    // merged converts: weights + x(+colsum partials), one launch
    cvt_kernel<<<16896, blk>>>(qkvw, projw, x);

    // exact colsum chain
    xsum_final_kernel<<<BB * CC / 256, blk>>>();
    vsumx_kernel<<<BB * CC / 8, blk>>>(qkvw);
    vsumw_kernel<<<BB * CC / 8, blk>>>(projw);

    // qkv projection with fused norm/split/sort epilogue
    gemm1p_kernel<2><<<dim3(3 * CC / 128, M_ROWS / 128), blk, GEMM1P_SMEM>>>(
        xh, w1h, nullptr, 0, nullptr, nullptr, nullptr);

    // paired-q-tile attention: one balanced wave
    attn_mma_kernel<<<dim3(8, BB * HH), blk, ATTN_SMEM_BYTES>>>(um);

    // output projection: out = dev.W2^T + invl*vsumw + bias
    gemm1p_kernel<1><<<dim3(CC / 128, M_ROWS / 128), blk, GEMM1P_SMEM>>>(
        dev, w2h, out, CC, invl, vsumw, projb);
}

// round 16
// speedup vs baseline: 1.0220x; 1.0220x over previous
#include <cuda_runtime.h>
#include <cuda_bf16.h>
#include <stdint.h>
#include <math.h>

#define BB 2
#define NN 2048
#define CC 1024
#define HH 16
#define HD 64
#define M_ROWS (BB*NN)   // 4096

// ---------------- device scratch (allocation-free) ----------------
__device__ __nv_bfloat16 g_x_hi[M_ROWS * CC];
__device__ __nv_bfloat16 g_w1_hi[3 * CC * CC];
__device__ __nv_bfloat16 g_w2_hi[CC * CC];
// head-major [b*H+h][sorted n][64] bf16
__device__ __nv_bfloat16 g_qn[BB * HH * NN * HD];
__device__ __nv_bfloat16 g_kn[BB * HH * NN * HD];
__device__ __nv_bfloat16 g_vh[BB * HH * NN * HD];
__device__ float g_xsum[BB * CC];                     // colsum of x (atomic)
__device__ float g_vsum[BB * CC];                     // exact colsum of V
__device__ float g_vsumw[BB * CC];                    // vsum . W2^T
// score sort
__device__ float g_ssort[NN];
__device__ int   g_perm[NN];
__device__ int   g_inv[NN];
// attention deviation output (bf16) + per-row 1/l
__device__ __nv_bfloat16 g_dev[M_ROWS * CC];
__device__ float g_invl[M_ROWS];

// ---------------------------------------------------------------------------
// Bitonic sort of 2048 scores (descending); also zeroes g_xsum (globals
// persist across graph replays, so the atomic accumulator must be reset).
// ---------------------------------------------------------------------------
__global__ __launch_bounds__(1024) void sort_kernel(const float* __restrict__ cls)
{
    __shared__ float ss[NN];
    __shared__ int   si[NN];
    int tid = threadIdx.x;
    g_xsum[tid] = 0.0f;
    g_xsum[tid + 1024] = 0.0f;
    for (int i = tid; i < NN; i += 1024) { ss[i] = cls[i]; si[i] = i; }
    __syncthreads();
    for (int k = 2; k <= NN; k <<= 1) {
        for (int j = k >> 1; j > 0; j >>= 1) {
            for (int i = tid; i < NN; i += 1024) {
                int ixj = i ^ j;
                if (ixj > i) {
                    bool up = ((i & k) == 0);
                    float a = ss[i], c = ss[ixj];
                    bool sw = up ? (a < c) : (a > c);
                    if (sw) {
                        ss[i] = c; ss[ixj] = a;
                        int t = si[i]; si[i] = si[ixj]; si[ixj] = t;
                    }
                }
            }
            __syncthreads();
        }
    }
    for (int i = tid; i < NN; i += 1024) {
        g_ssort[i] = ss[i];
        g_perm[i] = si[i];
        g_inv[si[i]] = i;
    }
}

// ---------------------------------------------------------------------------
// Merged converts: blocks [0,16384) convert w1|w2; blocks [16384,16896)
// convert x -> bf16 and atomically accumulate column sums into g_xsum.
// ---------------------------------------------------------------------------
__global__ __launch_bounds__(256) void cvt_kernel(
    const float* __restrict__ w1, const float* __restrict__ w2,
    const float* __restrict__ x)
{
    int bid = blockIdx.x;
    int tid = threadIdx.x;
    if (bid < 16384) {
        int i = bid * 256 + tid;
        const int n1 = 3 * CC * CC;
        if (i < n1) g_w1_hi[i] = __float2bfloat16(w1[i]);
        else        g_w2_hi[i - n1] = __float2bfloat16(w2[i - n1]);
    } else {
        int b2 = bid - 16384;             // 0..511
        int chunk = b2 >> 3;              // 0..63
        int c = (b2 & 7) * 256 + tid;     // 0..2047
        int b = c >> 10;
        size_t base = (size_t)b * NN * CC + (size_t)chunk * 32 * CC + (c & 1023);
        float s = 0.0f;
        #pragma unroll 8
        for (int n = 0; n < 32; ++n) {
            float v = x[base + (size_t)n * CC];
            g_x_hi[base + (size_t)n * CC] = __float2bfloat16(v);
            s += v;
        }
        atomicAdd(&g_xsum[c], s);
    }
}

// ---------------- mma helpers ----------------
__device__ __forceinline__ unsigned smem_u32(const void* p) {
    return (unsigned)__cvta_generic_to_shared(p);
}
__device__ __forceinline__ void cp16(void* smem, const void* gmem) {
    unsigned sa = smem_u32(smem);
    asm volatile("cp.async.cg.shared.global [%0], [%1], 16;\n" :: "r"(sa), "l"(gmem));
}
__device__ __forceinline__ void ldsm4(unsigned r[4], const void* p) {
    unsigned a = smem_u32(p);
    asm volatile("ldmatrix.sync.aligned.m8n8.x4.shared.b16 {%0,%1,%2,%3}, [%4];"
                 : "=r"(r[0]), "=r"(r[1]), "=r"(r[2]), "=r"(r[3]) : "r"(a));
}
__device__ __forceinline__ void ldsm4t(unsigned r[4], const void* p) {
    unsigned a = smem_u32(p);
    asm volatile("ldmatrix.sync.aligned.m8n8.x4.trans.shared.b16 {%0,%1,%2,%3}, [%4];"
                 : "=r"(r[0]), "=r"(r[1]), "=r"(r[2]), "=r"(r[3]) : "r"(a));
}
__device__ __forceinline__ void mma16816(float c[4], const unsigned a[4],
                                         unsigned b0, unsigned b1) {
    asm volatile(
        "mma.sync.aligned.m16n8k16.row.col.f32.bf16.bf16.f32 "
        "{%0,%1,%2,%3}, {%4,%5,%6,%7}, {%8,%9}, {%0,%1,%2,%3};"
        : "+f"(c[0]), "+f"(c[1]), "+f"(c[2]), "+f"(c[3])
        : "r"(a[0]), "r"(a[1]), "r"(a[2]), "r"(a[3]), "r"(b0), "r"(b1));
}
// delta = exp(t)-1 for |t|<=0.125 via cubic (residual <= t^4/24 ~ 1e-5)
__device__ __forceinline__ float expm1c(float t) {
    return t * fmaf(t, fmaf(t, 0.16666667f, 0.5f), 1.0f);
}

// warp-strided GEMV helper: out[gw] = src[b,:] . W[row(gw),:]  (fp32)
__device__ __forceinline__ void gemv_warps(
    const float* __restrict__ src, const float* __restrict__ W, int wrow_off,
    float* __restrict__ dst, int gwi, int gstride)
{
    int lane = threadIdx.x & 31;
    for (int gw = gwi; gw < BB * CC; gw += gstride) {
        int b = gw >> 10, d = gw & 1023;
        const float* wr = W + (size_t)(wrow_off + d) * CC;
        const float* sr = src + b * CC;
        float s = 0.0f;
        #pragma unroll 8
        for (int i = lane; i < CC; i += 32) s += sr[i] * wr[i];
        #pragma unroll
        for (int o = 16; o; o >>= 1) s += __shfl_xor_sync(0xffffffffu, s, o);
        if (lane == 0) dst[gw] = s;
    }
}

#define GLDA 40
#define TILE_B (128 * GLDA * 2)   // 10240 B per 128x32 bf16 tile

// ---------------------------------------------------------------------------
// Single-pass bf16 GEMM (NT), 4-stage cp.async pipeline, 2 CTAs/SM.
// MODE=1: C = A B^T + invl[m]*vsumw[b][n] + bias[n]   (output projection)
// MODE=2: qkv fused epilogue (norm/split/sort-permute), no C write.
//         Grid y==32 blocks instead run vsumx: g_vsum = g_xsum . Wv^T
//         (ordered after cvt_kernel by the stream; wf = fp32 qkv weights).
// ---------------------------------------------------------------------------
template<int MODE>
__global__ __launch_bounds__(256, 2) void gemm1p_kernel(
    const __nv_bfloat16* __restrict__ A, const __nv_bfloat16* __restrict__ Bm,
    float* __restrict__ C, int Nn,
    const float* __restrict__ invl, const float* __restrict__ vsumw,
    const float* __restrict__ bias, const float* __restrict__ wf)
{
    extern __shared__ char sm_raw[];
    const int STAGE = 2 * TILE_B;
    int tid = threadIdx.x;
    int lane = tid & 31;
    int wid = tid >> 5;

    if (MODE == 2 && blockIdx.y == 32) {
        // vsumx side-work: 24 blocks * 8 warps = 192 warps over 2048 outputs
        gemv_warps(g_xsum, wf, 2048, g_vsum, blockIdx.x * 8 + wid, 192);
        return;
    }

    int warp_m = wid >> 2;
    int warp_n = wid & 3;
    int m0 = blockIdx.y * 128;
    int n0 = blockIdx.x * 128;

    float acc[4][4][4];
    #pragma unroll
    for (int mi = 0; mi < 4; ++mi)
        #pragma unroll
        for (int j = 0; j < 4; ++j)
            #pragma unroll
            for (int e = 0; e < 4; ++e) acc[mi][j][e] = 0.0f;

    auto load_stage = [&](int kt, int s) {
        char* sb = sm_raw + s * STAGE;
        int k0 = kt * 32;
        #pragma unroll
        for (int t = 0; t < 4; ++t) {
            int c = tid + t * 256;
            int arr = c >> 9;
            int r = (c >> 2) & 127;
            int c16 = c & 3;
            const __nv_bfloat16* g =
                (arr ? Bm : A) + (size_t)((arr ? n0 : m0) + r) * CC + k0 + c16 * 8;
            cp16(sb + arr * TILE_B + r * (GLDA * 2) + c16 * 16, g);
        }
    };

    const int KT = CC / 32;
    load_stage(0, 0); asm volatile("cp.async.commit_group;");
    load_stage(1, 1); asm volatile("cp.async.commit_group;");
    load_stage(2, 2); asm volatile("cp.async.commit_group;");

    for (int kt = 0; kt < KT; ++kt) {
        if (kt + 2 < KT)      asm volatile("cp.async.wait_group 2;");
        else if (kt + 1 < KT) asm volatile("cp.async.wait_group 1;");
        else                  asm volatile("cp.async.wait_group 0;");
        __syncthreads();
        const char* As = sm_raw + (kt & 3) * STAGE;
        const char* Bs = As + TILE_B;

        #pragma unroll
        for (int ks = 0; ks < 32; ks += 16) {
            int coloff = ks + ((lane >> 4) << 3);
            unsigned ah[4][4];
            #pragma unroll
            for (int mi = 0; mi < 4; ++mi)
                ldsm4(ah[mi], As + (warp_m * 64 + mi * 16 + (lane & 15)) * (GLDA * 2)
                               + coloff * 2);
            unsigned bh[2][4];
            #pragma unroll
            for (int ni = 0; ni < 2; ++ni)
                ldsm4(bh[ni], Bs + (warp_n * 32 + ni * 16 + (lane & 15)) * (GLDA * 2)
                               + coloff * 2);
            #pragma unroll
            for (int mi = 0; mi < 4; ++mi)
                #pragma unroll
                for (int j = 0; j < 4; ++j) {
                    int ni = j >> 1, od = j & 1;
                    mma16816(acc[mi][j], ah[mi],
                             bh[ni][od ? 1 : 0], bh[ni][od ? 3 : 2]);
                }
        }
        if (kt + 3 < KT) {
            load_stage(kt + 3, (kt + 3) & 3);
            asm volatile("cp.async.commit_group;");
        }
    }

    if (MODE == 1) {
        int mb = m0 + warp_m * 64 + (lane >> 2);
        int nb = n0 + warp_n * 32 + 2 * (lane & 3);
        #pragma unroll
        for (int mi = 0; mi < 4; ++mi)
            #pragma unroll
            for (int j = 0; j < 4; ++j) {
                int col = nb + j * 8;
                int r0 = mb + mi * 16;
                int b = r0 >> 11;
                float b0 = bias[col], b1 = bias[col + 1];
                float vw0 = vsumw[b * CC + col], vw1 = vsumw[b * CC + col + 1];
                float il0 = invl[r0], il8 = invl[r0 + 8];
                float a0 = acc[mi][j][0] + il0 * vw0 + b0;
                float a1 = acc[mi][j][1] + il0 * vw1 + b1;
                float a2 = acc[mi][j][2] + il8 * vw0 + b0;
                float a3 = acc[mi][j][3] + il8 * vw1 + b1;
                *reinterpret_cast<float2*>(&C[(size_t)r0 * Nn + col]) =
                    make_float2(a0, a1);
                *reinterpret_cast<float2*>(&C[(size_t)(r0 + 8) * Nn + col]) =
                    make_float2(a2, a3);
            }
    } else {
        int part = n0 >> 10;                     // 0=q, 1=k, 2=v
        int h = ((n0 & 1023) >> 6) + (warp_n >> 1);
        float* red = (float*)sm_raw;
        __syncthreads();

        if (part < 2) {
            #pragma unroll
            for (int mi = 0; mi < 4; ++mi) {
                float s0 = 0.0f, s8 = 0.0f;
                #pragma unroll
                for (int j = 0; j < 4; ++j) {
                    s0 += acc[mi][j][0] * acc[mi][j][0] + acc[mi][j][1] * acc[mi][j][1];
                    s8 += acc[mi][j][2] * acc[mi][j][2] + acc[mi][j][3] * acc[mi][j][3];
                }
                s0 += __shfl_xor_sync(0xffffffffu, s0, 1);
                s0 += __shfl_xor_sync(0xffffffffu, s0, 2);
                s8 += __shfl_xor_sync(0xffffffffu, s8, 1);
                s8 += __shfl_xor_sync(0xffffffffu, s8, 2);
                if ((lane & 3) == 0) {
                    int lr = warp_m * 64 + mi * 16 + (lane >> 2);
                    red[warp_n * 128 + lr] = s0;
                    red[warp_n * 128 + lr + 8] = s8;
                }
            }
            __syncthreads();
        }

        float qsc = (part == 0) ? 0.125f : 1.0f;
        __nv_bfloat16* dst = (part == 0) ? g_qn : (part == 1 ? g_kn : g_vh);
        int pbase = (warp_n & 2) * 128;
        int dbase = (warp_n & 1) * 32 + 2 * (lane & 3);

        #pragma unroll
        for (int mi = 0; mi < 4; ++mi) {
            int lr0 = warp_m * 64 + mi * 16 + (lane >> 2);
            int r0 = m0 + lr0;
            float inv0 = 1.0f, inv8 = 1.0f;
            if (part < 2) {
                float s0 = red[pbase + lr0] + red[pbase + 128 + lr0];
                float s8 = red[pbase + lr0 + 8] + red[pbase + 128 + lr0 + 8];
                inv0 = qsc / (sqrtf(s0) + 1e-8f);
                inv8 = qsc / (sqrtf(s8) + 1e-8f);
            }
            int b = r0 >> 11;
            int pos0 = g_inv[r0 & 2047];
            int pos8 = g_inv[(r0 + 8) & 2047];
            size_t base0 = ((size_t)(b * HH + h) * NN + pos0) * 64;
            size_t base8 = ((size_t)(b * HH + h) * NN + pos8) * 64;
            #pragma unroll
            for (int j = 0; j < 4; ++j) {
                int d = dbase + j * 8;
                __nv_bfloat162 v0 =
                    __floats2bfloat162_rn(acc[mi][j][0] * inv0, acc[mi][j][1] * inv0);
                __nv_bfloat162 v8 =
                    __floats2bfloat162_rn(acc[mi][j][2] * inv8, acc[mi][j][3] * inv8);
                *reinterpret_cast<__nv_bfloat162*>(dst + base0 + d) = v0;
                *reinterpret_cast<__nv_bfloat162*>(dst + base8 + d) = v8;
            }
        }
    }
}

// ---------------------------------------------------------------------------
// Attention tile body. MASK=false: full-tile fast path (no SELs).
// ---------------------------------------------------------------------------
#define ATS 72
#define KTB (128 * ATS * 2)

template<bool MASK>
__device__ __forceinline__ void attn_tile(
    const char* Kb, const char* Vhb, const float* sk,
    const unsigned qa[4][4], float sq0, float sq8,
    float o[8][4], float& l0, float& l8, int lane, int c2)
{
    #pragma unroll
    for (int j = 0; j < 8; ++j) {
        float cc[2][4] = {{0, 0, 0, 0}, {0, 0, 0, 0}};
        int krow = 16 * j + (lane & 15);
        #pragma unroll
        for (int dc = 0; dc < 4; ++dc) {
            unsigned kb[4];
            ldsm4(kb, Kb + krow * (ATS * 2) + (16 * dc + ((lane >> 4) << 3)) * 2);
            mma16816(cc[0], qa[dc], kb[0], kb[2]);
            mma16816(cc[1], qa[dc], kb[1], kb[3]);
        }
        unsigned vb[4][4];
        #pragma unroll
        for (int n2 = 0; n2 < 4; ++n2)
            ldsm4t(vb[n2], Vhb + krow * (ATS * 2)
                           + (16 * n2 + ((lane >> 4) << 3)) * 2);
        unsigned ad[4];
        #pragma unroll
        for (int t = 0; t < 2; ++t) {
            float2 skv = *reinterpret_cast<const float2*>(&sk[16 * j + 8 * t + c2]);
            float fx0 = skv.x, fy0 = skv.y, fx8 = skv.x, fy8 = skv.y;
            if (MASK) {
                fx0 = (skv.x > sq0) ? skv.x : 0.0f;
                fy0 = (skv.y > sq0) ? skv.y : 0.0f;
                fx8 = (skv.x > sq8) ? skv.x : 0.0f;
                fy8 = (skv.y > sq8) ? skv.y : 0.0f;
            }
            float d00 = expm1c(cc[t][0] * fx0);
            float d01 = expm1c(cc[t][1] * fy0);
            float d80 = expm1c(cc[t][2] * fx8);
            float d81 = expm1c(cc[t][3] * fy8);
            l0 += d00 + d01;
            l8 += d80 + d81;
            __nv_bfloat162 D0 = __floats2bfloat162_rn(d00, d01);
            __nv_bfloat162 D8 = __floats2bfloat162_rn(d80, d81);
            ad[2 * t]     = *reinterpret_cast<unsigned*>(&D0);
            ad[2 * t + 1] = *reinterpret_cast<unsigned*>(&D8);
        }
        #pragma unroll
        for (int n2 = 0; n2 < 4; ++n2) {
            mma16816(o[2 * n2],     ad, vb[n2][0], vb[n2][1]);
            mma16816(o[2 * n2 + 1], ad, vb[n2][2], vb[n2][3]);
        }
    }
}

// ---------------------------------------------------------------------------
// Tensor-core attention, delta-trick + sorted prefix skipping, PAIRED q-tiles.
// Grid y==32 blocks instead run vsumw: g_vsumw = g_vsum . W2^T
// (ordered after gemm<2>'s vsumx blocks by the stream).
// ---------------------------------------------------------------------------
__global__ __launch_bounds__(256, 2) void attn_mma_kernel(
    const int* __restrict__ um_p, const float* __restrict__ w2f)
{
    extern __shared__ char smem[];
    float* sks = (float*)(smem + 4 * KTB);
    __shared__ float sh_full[2][16];
    __shared__ int sh_ktstop[2];

    int tid = threadIdx.x;
    int lane = tid & 31;
    int warp = tid >> 5;

    if (blockIdx.y == 32) {
        // vsumw side-work: 8 blocks * 8 warps = 64 warps over 2048 outputs
        gemv_warps(g_vsum, w2f, 0, g_vsumw, blockIdx.x * 8 + warp, 64);
        return;
    }

    int qpair = blockIdx.x;                // 0..7
    int bh = blockIdx.y;
    int b = bh >> 4, h = bh & 15;
    int um = um_p[0];
    int r = lane >> 2;
    int c2 = 2 * (lane & 3);

    if (tid < 2) {
        int qt = tid ? (15 - qpair) : qpair;
        float sqmin = g_ssort[qt * 128 + 127];
        int ks = 16;
        if (um) {
            for (int t = 1; t < 16; ++t)
                if (g_ssort[t * 128] <= sqmin - 0.1f) { ks = t; break; }
        }
        sh_ktstop[tid] = ks;
    }
    if (tid < 32) {
        int hf = tid >> 4, t = tid & 15;
        int qt = hf ? (15 - qpair) : qpair;
        float sqmax = g_ssort[qt * 128];
        float skmin = g_ssort[t * 128 + 127];
        sh_full[hf][t] = (um == 0 || skmin > sqmax - 0.1f) ? 1.0f : 0.0f;
    }

    const __nv_bfloat16* kg  = g_kn + (size_t)bh * NN * 64;
    const __nv_bfloat16* vhg = g_vh + (size_t)bh * NN * 64;

    auto stage_load = [&](int kt, int s) {
        #pragma unroll
        for (int t = 0; t < 8; ++t) {
            int cix = tid + t * 256;
            int arr = cix >> 10;
            int rr  = (cix >> 3) & 127;
            int seg = cix & 7;
            const __nv_bfloat16* gb = (arr == 0) ? kg : vhg;
            const __nv_bfloat16* g = gb + ((size_t)(kt * 128 + rr)) * 64 + seg * 8;
            cp16(smem + arr * 2 * KTB + s * KTB + rr * (ATS * 2) + seg * 16, g);
        }
        if (tid < 128) sks[s * 128 + tid] = g_ssort[kt * 128 + tid];
    };

    for (int hf = 0; hf < 2; ++hf) {
        int q0 = (hf ? (15 - qpair) : qpair) * 128;

        const __nv_bfloat16* qg = g_qn + ((size_t)bh * NN + q0 + warp * 16) * 64;
        unsigned qa[4][4];
        #pragma unroll
        for (int dc = 0; dc < 4; ++dc) {
            qa[dc][0] = *(const unsigned*)(qg + (size_t)r * 64 + 16 * dc + c2);
            qa[dc][1] = *(const unsigned*)(qg + (size_t)(r + 8) * 64 + 16 * dc + c2);
            qa[dc][2] = *(const unsigned*)(qg + (size_t)r * 64 + 16 * dc + 8 + c2);
            qa[dc][3] = *(const unsigned*)(qg + (size_t)(r + 8) * 64 + 16 * dc + 8 + c2);
        }
        float sq0 = g_ssort[q0 + warp * 16 + r] - 0.1f;
        float sq8 = g_ssort[q0 + warp * 16 + r + 8] - 0.1f;

        float o[8][4];
        #pragma unroll
        for (int i = 0; i < 8; ++i)
            #pragma unroll
            for (int e = 0; e < 4; ++e) o[i][e] = 0.0f;
        float l0 = 0.0f, l8 = 0.0f;

        __syncthreads();
        const int KTS = sh_ktstop[hf];

        stage_load(0, 0);
        asm volatile("cp.async.commit_group;");

        for (int kt = 0; kt < KTS; ++kt) {
            asm volatile("cp.async.wait_group 0;");
            __syncthreads();
            if (kt + 1 < KTS) {
                stage_load(kt + 1, (kt + 1) & 1);
                asm volatile("cp.async.commit_group;");
            }
            int s = kt & 1;
            const char* Kb  = smem + s * KTB;
            const char* Vhb = smem + 2 * KTB + s * KTB;
            const float* sk = sks + s * 128;
            if (sh_full[hf][kt] != 0.0f)
                attn_tile<false>(Kb, Vhb, sk, qa, sq0, sq8, o, l0, l8, lane, c2);
            else
                attn_tile<true>(Kb, Vhb, sk, qa, sq0, sq8, o, l0, l8, lane, c2);
        }

        l0 += __shfl_xor_sync(0xffffffffu, l0, 1);
        l0 += __shfl_xor_sync(0xffffffffu, l0, 2);
        l8 += __shfl_xor_sync(0xffffffffu, l8, 1);
        l8 += __shfl_xor_sync(0xffffffffu, l8, 2);
        float inv0 = 1.0f / ((float)NN + l0);
        float inv8 = 1.0f / ((float)NN + l8);

        int qrow = q0 + warp * 16 + r;
        int orig0 = g_perm[qrow];
        int orig8 = g_perm[qrow + 8];
        size_t tok0 = (size_t)(b * NN + orig0);
        size_t tok8 = (size_t)(b * NN + orig8);
        if ((lane & 3) == 0) {
            g_invl[tok0] = inv0;
            g_invl[tok8] = inv8;
        }
        size_t row0 = tok0 * CC + h * 64;
        size_t row8 = tok8 * CC + h * 64;
        #pragma unroll
        for (int nt = 0; nt < 8; ++nt) {
            int d = 8 * nt + c2;
            *reinterpret_cast<__nv_bfloat162*>(&g_dev[row0 + d]) =
                __floats2bfloat162_rn(o[nt][0] * inv0, o[nt][1] * inv0);
            *reinterpret_cast<__nv_bfloat162*>(&g_dev[row8 + d]) =
                __floats2bfloat162_rn(o[nt][2] * inv8, o[nt][3] * inv8);
        }
    }
}

// ---------------------------------------------------------------------------
// Launch: 5 kernels total.
// ---------------------------------------------------------------------------
static const int GEMM1P_SMEM = 4 * 2 * TILE_B;
static const int ATTN_SMEM_BYTES = 4 * KTB + 2 * 128 * (int)sizeof(float);

extern "C" void kernel_launch(void* const* d_in, const int* in_sizes, int n_in,
                              void* d_out, int out_size)
{
    const float* x     = (const float*)d_in[0];
    const float* cls   = (const float*)d_in[1];
    const float* qkvw  = (const float*)d_in[2];
    const float* projw = (const float*)d_in[3];
    const float* projb = (const float*)d_in[4];
    const int*   um    = (const int*)d_in[5];
    float* out = (float*)d_out;

    float *invl, *vsumw;
    __nv_bfloat16 *xh, *w1h, *w2h, *dev;
    cudaGetSymbolAddress((void**)&xh,    g_x_hi);
    cudaGetSymbolAddress((void**)&w1h,   g_w1_hi);
    cudaGetSymbolAddress((void**)&w2h,   g_w2_hi);
    cudaGetSymbolAddress((void**)&dev,   g_dev);
    cudaGetSymbolAddress((void**)&invl,  g_invl);
    cudaGetSymbolAddress((void**)&vsumw, g_vsumw);

    cudaFuncSetAttribute(gemm1p_kernel<1>,
                         cudaFuncAttributeMaxDynamicSharedMemorySize, GEMM1P_SMEM);
    cudaFuncSetAttribute(gemm1p_kernel<2>,
                         cudaFuncAttributeMaxDynamicSharedMemorySize, GEMM1P_SMEM);
    cudaFuncSetAttribute(attn_mma_kernel,
                         cudaFuncAttributeMaxDynamicSharedMemorySize, ATTN_SMEM_BYTES);

    dim3 blk(256);

    // 1) score sort + zero xsum accumulator
    sort_kernel<<<1, 1024>>>(cls);

    // 2) merged converts (weights + x) with atomic colsum
    cvt_kernel<<<16896, blk>>>(qkvw, projw, x);

    // 3) qkv projection + fused norm/split/sort epilogue; y==32 blocks: vsumx
    gemm1p_kernel<2><<<dim3(3 * CC / 128, 33), blk, GEMM1P_SMEM>>>(
        xh, w1h, nullptr, 0, nullptr, nullptr, nullptr, qkvw);

    // 4) paired-q-tile attention; y==32 blocks: vsumw
    attn_mma_kernel<<<dim3(8, 33), blk, ATTN_SMEM_BYTES>>>(um, projw);

    // 5) output projection: out = dev.W2^T + invl*vsumw + bias
    gemm1p_kernel<1><<<dim3(CC / 128, 32), blk, GEMM1P_SMEM>>>(
        dev, w2h, out, CC, invl, vsumw, projb, nullptr);
}